// round 3
// baseline (speedup 1.0000x reference)
#include <cuda_runtime.h>

// Problem shape (fixed by the dataset): Na=Nb=4096, Fa=Fb=512, D=128, E=131072
#define NMAX  4096
#define DV    128
#define NPART 64

__device__ __align__(16) float g_ha[NMAX * DV];
__device__ __align__(16) float g_hb[NMAX * DV];
__device__ __align__(16) float g_t [NMAX * DV];
__device__ __align__(16) int   g_deg[NMAX];
__device__ __align__(16) int   g_part[NPART][NMAX];
__device__ int g_mode64;   // 1 if edge indices are int64, 0 if int32

// ---------------------------------------------------------------------------
// Zero scratch (t, deg) and the output buffer; block 0 additionally detects
// int64-vs-int32 edge encoding (indices < 4096 => odd 32-bit words all zero
// iff little-endian int64). Sample 2048 words.
// ---------------------------------------------------------------------------
__global__ void zero_detect_kernel(float* __restrict__ out, int n,
                                   const int* __restrict__ e, int nwords) {
    int i = blockIdx.x * blockDim.x + threadIdx.x;
    float4 z = make_float4(0.f, 0.f, 0.f, 0.f);
    int n4 = n >> 2;
    if (i < n4) {
        ((float4*)out)[i] = z;
        ((float4*)g_t)[i] = z;
    }
    if (blockIdx.x == 0) {
        __shared__ int any;
        if (threadIdx.x == 0) any = 0;
        __syncthreads();
        int hit = 0;
        for (int w = 1 + 2 * threadIdx.x; w < nwords; w += 2 * blockDim.x)
            if (e[w] != 0) hit = 1;
        if (hit) any = 1;
        __syncthreads();
        if (threadIdx.x == 0) g_mode64 = (any == 0) ? 1 : 0;
    }
}

// ---------------------------------------------------------------------------
// Fused dual GEMM + bias + relu:
//   g_ha = relu(Xa @ Wa + ba)   (blocks [0, blocksPer))
//   g_hb = relu(Xb @ Wb + bb)   (blocks [blocksPer, 2*blocksPer))
// Tile: BM=64 x BN=128, BK=16, 256 threads, 8x4 per thread, packed f32x2 FMA.
// ---------------------------------------------------------------------------
__global__ void __launch_bounds__(256) gemm2_relu_kernel(
    const float* __restrict__ Xa, const float* __restrict__ Wa, const float* __restrict__ ba,
    const float* __restrict__ Xb, const float* __restrict__ Wb, const float* __restrict__ bb,
    int K, int blocksPer)
{
    constexpr int BM = 64, BN = 128, BK = 16;
    __shared__ float As[2][BK][68];
    __shared__ float Bs[2][BK][BN];

    const int which = (blockIdx.x >= blocksPer) ? 1 : 0;
    const float* __restrict__ X    = which ? Xb : Xa;
    const float* __restrict__ W    = which ? Wb : Wa;
    const float* __restrict__ bias = which ? bb : ba;
    float* __restrict__ H          = which ? g_hb : g_ha;

    const int bm = (blockIdx.x - which * blocksPer) * BM;
    const int t  = threadIdx.x;
    const int tx = t & 31;
    const int ty = t >> 5;

    const int rowA = t >> 2;
    const int c4A  = t & 3;
    const int kkB0 = t >> 5;
    const int c4B  = t & 31;

    const int nT = K / BK;

    unsigned long long acc[4][4];
#pragma unroll
    for (int p = 0; p < 4; p++)
#pragma unroll
        for (int j = 0; j < 4; j++) acc[p][j] = 0ULL;

    const float* Aptr  = X + (size_t)(bm + rowA) * K + c4A * 4;
    const float* Bptr0 = W + (size_t)kkB0 * BN + c4B * 4;
    const float* Bptr1 = W + (size_t)(kkB0 + 8) * BN + c4B * 4;

    float4 av  = *(const float4*)(Aptr);
    float4 bv0 = *(const float4*)(Bptr0);
    float4 bv1 = *(const float4*)(Bptr1);

    As[0][c4A * 4 + 0][rowA] = av.x;
    As[0][c4A * 4 + 1][rowA] = av.y;
    As[0][c4A * 4 + 2][rowA] = av.z;
    As[0][c4A * 4 + 3][rowA] = av.w;
    *(float4*)&Bs[0][kkB0][c4B * 4]     = bv0;
    *(float4*)&Bs[0][kkB0 + 8][c4B * 4] = bv1;
    __syncthreads();

    int cur = 0;
    for (int tt = 0; tt < nT; tt++) {
        if (tt + 1 < nT) {
            int k0n = (tt + 1) * BK;
            av  = *(const float4*)(Aptr + k0n);
            bv0 = *(const float4*)(Bptr0 + (size_t)k0n * BN);
            bv1 = *(const float4*)(Bptr1 + (size_t)k0n * BN);
        }

#pragma unroll
        for (int kk = 0; kk < BK; kk++) {
            ulonglong2 a01 = *(const ulonglong2*)&As[cur][kk][ty * 8];
            ulonglong2 a23 = *(const ulonglong2*)&As[cur][kk][ty * 8 + 4];
            float4 b = *(const float4*)&Bs[cur][kk][tx * 4];
            unsigned long long B0, B1, B2, B3;
            asm("mov.b64 %0, {%1, %1};" : "=l"(B0) : "f"(b.x));
            asm("mov.b64 %0, {%1, %1};" : "=l"(B1) : "f"(b.y));
            asm("mov.b64 %0, {%1, %1};" : "=l"(B2) : "f"(b.z));
            asm("mov.b64 %0, {%1, %1};" : "=l"(B3) : "f"(b.w));
            unsigned long long ap[4] = {a01.x, a01.y, a23.x, a23.y};
#pragma unroll
            for (int p = 0; p < 4; p++) {
                asm("fma.rn.f32x2 %0, %1, %2, %0;" : "+l"(acc[p][0]) : "l"(ap[p]), "l"(B0));
                asm("fma.rn.f32x2 %0, %1, %2, %0;" : "+l"(acc[p][1]) : "l"(ap[p]), "l"(B1));
                asm("fma.rn.f32x2 %0, %1, %2, %0;" : "+l"(acc[p][2]) : "l"(ap[p]), "l"(B2));
                asm("fma.rn.f32x2 %0, %1, %2, %0;" : "+l"(acc[p][3]) : "l"(ap[p]), "l"(B3));
            }
        }

        if (tt + 1 < nT) {
            int nxt = cur ^ 1;
            As[nxt][c4A * 4 + 0][rowA] = av.x;
            As[nxt][c4A * 4 + 1][rowA] = av.y;
            As[nxt][c4A * 4 + 2][rowA] = av.z;
            As[nxt][c4A * 4 + 3][rowA] = av.w;
            *(float4*)&Bs[nxt][kkB0][c4B * 4]     = bv0;
            *(float4*)&Bs[nxt][kkB0 + 8][c4B * 4] = bv1;
        }
        __syncthreads();
        cur ^= 1;
    }

    float4 bvb = *(const float4*)(bias + tx * 4);
#pragma unroll
    for (int p = 0; p < 4; p++) {
        float lo[4], hi[4];
#pragma unroll
        for (int j = 0; j < 4; j++) {
            float l, h;
            asm("mov.b64 {%0, %1}, %2;" : "=f"(l), "=f"(h) : "l"(acc[p][j]));
            lo[j] = l; hi[j] = h;
        }
        int r0 = bm + ty * 8 + 2 * p;
        float4 o0, o1;
        o0.x = fmaxf(lo[0] + bvb.x, 0.f); o0.y = fmaxf(lo[1] + bvb.y, 0.f);
        o0.z = fmaxf(lo[2] + bvb.z, 0.f); o0.w = fmaxf(lo[3] + bvb.w, 0.f);
        o1.x = fmaxf(hi[0] + bvb.x, 0.f); o1.y = fmaxf(hi[1] + bvb.y, 0.f);
        o1.z = fmaxf(hi[2] + bvb.z, 0.f); o1.w = fmaxf(hi[3] + bvb.w, 0.f);
        *(float4*)(H + (size_t)r0 * DV + tx * 4)       = o0;
        *(float4*)(H + (size_t)(r0 + 1) * DV + tx * 4) = o1;
    }
}

// ---------------------------------------------------------------------------
// Degree histogram, privatized: NPART blocks, each builds a 4096-entry smem
// histogram over its slice of the 2E index stream (eab cols ++ eba rows),
// then stores its partial with plain coalesced stores.
// ---------------------------------------------------------------------------
__global__ void __launch_bounds__(256) deg_part_kernel(
    const int* __restrict__ eab, const int* __restrict__ eba, int E)
{
    __shared__ int h[NMAX];
    const int t = threadIdx.x;
    for (int i = t; i < NMAX; i += blockDim.x) h[i] = 0;
    __syncthreads();

    const int s = g_mode64 ? 2 : 1;
    const int total = 2 * E;
    const int per = (total + NPART - 1) / NPART;
    const int lo = blockIdx.x * per;
    const int hi = min(lo + per, total);

    for (int j = lo + t; j < hi; j += blockDim.x) {
        int idx;
        if (j < E) idx = eab[(size_t)(E + j) * s];        // edge_ab[1][j]
        else       idx = eba[(size_t)(j - E) * s];        // edge_ba[0][j-E]
        atomicAdd(&h[idx], 1);
    }
    __syncthreads();

    for (int i = t; i < NMAX; i += blockDim.x) g_part[blockIdx.x][i] = h[i];
}

// 4096 threads: g_deg[i] = sum_p g_part[p][i] (coalesced in i).
__global__ void deg_reduce_kernel() {
    int i = blockIdx.x * blockDim.x + threadIdx.x;
    if (i >= NMAX) return;
    int s = 0;
#pragma unroll 8
    for (int p = 0; p < NPART; p++) s += g_part[p][i];
    g_deg[i] = s;
}

// ---------------------------------------------------------------------------
// t[row] += h_a[col] for each edge in edge_ba. One warp per edge,
// one red.global.add.v4.f32 (16B) per lane.
// ---------------------------------------------------------------------------
__global__ void scatter1_kernel(const int* __restrict__ e, int E) {
    int gw   = (blockIdx.x * blockDim.x + threadIdx.x) >> 5;
    int lane = threadIdx.x & 31;
    if (gw >= E) return;
    int s   = g_mode64 ? 2 : 1;
    int row = e[(size_t)gw * s];
    int col = e[(size_t)(E + gw) * s];
    float4 v = *(const float4*)(g_ha + (size_t)col * DV + lane * 4);
    float* p = g_t + (size_t)row * DV + lane * 4;
    asm volatile("red.global.add.v4.f32 [%0], {%1,%2,%3,%4};"
                 :: "l"(p), "f"(v.x), "f"(v.y), "f"(v.z), "f"(v.w) : "memory");
}

// ---------------------------------------------------------------------------
// t[i,:] = d(deg[i]) * t[i,:] + h_b[i,:]   (in place)
// ---------------------------------------------------------------------------
__global__ void combine_kernel(int n4) {
    int i = blockIdx.x * blockDim.x + threadIdx.x;
    if (i >= n4) return;
    int row = i >> 5;
    int deg = g_deg[row];
    float d = deg > 0 ? 1.0f / (float)deg : 0.0f;
    float4 tv = ((float4*)g_t)[i];
    float4 hb = ((float4*)g_hb)[i];
    float4 o;
    o.x = d * tv.x + hb.x;
    o.y = d * tv.y + hb.y;
    o.z = d * tv.z + hb.z;
    o.w = d * tv.w + hb.w;
    ((float4*)g_t)[i] = o;
}

// ---------------------------------------------------------------------------
// out[row] += t[col] for each edge in edge_ab.
// ---------------------------------------------------------------------------
__global__ void scatter2_kernel(const int* __restrict__ e, int E,
                                float* __restrict__ out) {
    int gw   = (blockIdx.x * blockDim.x + threadIdx.x) >> 5;
    int lane = threadIdx.x & 31;
    if (gw >= E) return;
    int s   = g_mode64 ? 2 : 1;
    int row = e[(size_t)gw * s];
    int col = e[(size_t)(E + gw) * s];
    float4 v = *(const float4*)(g_t + (size_t)col * DV + lane * 4);
    float* p = out + (size_t)row * DV + lane * 4;
    asm volatile("red.global.add.v4.f32 [%0], {%1,%2,%3,%4};"
                 :: "l"(p), "f"(v.x), "f"(v.y), "f"(v.z), "f"(v.w) : "memory");
}

// ---------------------------------------------------------------------------
extern "C" void kernel_launch(void* const* d_in, const int* in_sizes, int n_in,
                              void* d_out, int out_size) {
    const float* x_a = (const float*)d_in[0];
    const float* x_b = (const float*)d_in[1];
    const float* W_a = (const float*)d_in[2];
    const float* b_a = (const float*)d_in[3];
    const float* W_b = (const float*)d_in[4];
    const float* b_b = (const float*)d_in[5];
    const int*   eab = (const int*)d_in[6];
    const int*   eba = (const int*)d_in[7];
    float* out = (float*)d_out;

    const int D  = in_sizes[3];          // 128
    const int Fa = in_sizes[2] / D;      // 512
    const int Na = in_sizes[0] / Fa;     // 4096
    const int E  = in_sizes[6] / 2;      // 131072

    const int nElem = Na * D;

    // 1. zero t/out + dtype detection (fused)
    {
        int n4 = nElem / 4;
        int nw = 2 * E < 2048 ? 2 * E : 2048;
        zero_detect_kernel<<<(n4 + 255) / 256, 256>>>(out, nElem, eab, nw);
    }

    // 2. fused feature projections (both GEMMs in one launch, 1 wave)
    {
        int blocksPer = Na / 64;
        gemm2_relu_kernel<<<2 * blocksPer, 256>>>(x_a, W_a, b_a, x_b, W_b, b_b, Fa, blocksPer);
    }

    // 3. degree histogram (privatized partials + reduce)
    deg_part_kernel<<<NPART, 256>>>(eab, eba, E);
    deg_reduce_kernel<<<NMAX / 256, 256>>>();

    // 4. t = B @ h_a  (scatter over edge_ba)
    {
        long long thr = (long long)E * 32;
        scatter1_kernel<<<(unsigned)((thr + 255) / 256), 256>>>(eba, E);
    }

    // 5. t = d * t + h_b
    {
        int n4 = nElem / 4;
        combine_kernel<<<(n4 + 255) / 256, 256>>>(n4);
    }

    // 6. out = A @ t  (scatter over edge_ab)
    {
        long long thr = (long long)E * 32;
        scatter2_kernel<<<(unsigned)((thr + 255) / 256), 256>>>(eab, E, out);
    }
}

// round 4
// speedup vs baseline: 1.0266x; 1.0266x over previous
#include <cuda_runtime.h>

// Problem shape (fixed by the dataset): Na=Nb=4096, Fa=Fb=512, D=128, E=131072
#define NMAX  4096
#define DV    128
#define NPART 64

__device__ __align__(16) float g_ha[NMAX * DV];
__device__ __align__(16) float g_hb[NMAX * DV];
__device__ __align__(16) float g_t [NMAX * DV];
__device__ __align__(16) int   g_part[NPART][NMAX];
__device__ int g_mode64;   // 1 if edge indices are int64, 0 if int32

// ---------------------------------------------------------------------------
// Zero scratch (t) and the output buffer; block 0 additionally detects
// int64-vs-int32 edge encoding (indices < 4096 => odd 32-bit words all zero
// iff little-endian int64). Sample 2048 words.
// ---------------------------------------------------------------------------
__global__ void zero_detect_kernel(float* __restrict__ out, int n,
                                   const int* __restrict__ e, int nwords) {
    int i = blockIdx.x * blockDim.x + threadIdx.x;
    float4 z = make_float4(0.f, 0.f, 0.f, 0.f);
    int n4 = n >> 2;
    if (i < n4) {
        ((float4*)out)[i] = z;
        ((float4*)g_t)[i] = z;
    }
    if (blockIdx.x == 0) {
        __shared__ int any;
        if (threadIdx.x == 0) any = 0;
        __syncthreads();
        int hit = 0;
        for (int w = 1 + 2 * threadIdx.x; w < nwords; w += 2 * blockDim.x)
            if (e[w] != 0) hit = 1;
        if (hit) any = 1;
        __syncthreads();
        if (threadIdx.x == 0) g_mode64 = (any == 0) ? 1 : 0;
    }
}

// ---------------------------------------------------------------------------
// Fused dual GEMM + bias + relu:
//   g_ha = relu(Xa @ Wa + ba)   (blocks [0, blocksPer))
//   g_hb = relu(Xb @ Wb + bb)   (blocks [blocksPer, 2*blocksPer))
// Tile: BM=64 x BN=128, BK=16, 256 threads, 8x4 per thread, packed f32x2 FMA.
// ---------------------------------------------------------------------------
__global__ void __launch_bounds__(256) gemm2_relu_kernel(
    const float* __restrict__ Xa, const float* __restrict__ Wa, const float* __restrict__ ba,
    const float* __restrict__ Xb, const float* __restrict__ Wb, const float* __restrict__ bb,
    int K, int blocksPer)
{
    constexpr int BM = 64, BN = 128, BK = 16;
    __shared__ float As[2][BK][68];
    __shared__ float Bs[2][BK][BN];

    const int which = (blockIdx.x >= blocksPer) ? 1 : 0;
    const float* __restrict__ X    = which ? Xb : Xa;
    const float* __restrict__ W    = which ? Wb : Wa;
    const float* __restrict__ bias = which ? bb : ba;
    float* __restrict__ H          = which ? g_hb : g_ha;

    const int bm = (blockIdx.x - which * blocksPer) * BM;
    const int t  = threadIdx.x;
    const int tx = t & 31;
    const int ty = t >> 5;

    const int rowA = t >> 2;
    const int c4A  = t & 3;
    const int kkB0 = t >> 5;
    const int c4B  = t & 31;

    const int nT = K / BK;

    unsigned long long acc[4][4];
#pragma unroll
    for (int p = 0; p < 4; p++)
#pragma unroll
        for (int j = 0; j < 4; j++) acc[p][j] = 0ULL;

    const float* Aptr  = X + (size_t)(bm + rowA) * K + c4A * 4;
    const float* Bptr0 = W + (size_t)kkB0 * BN + c4B * 4;
    const float* Bptr1 = W + (size_t)(kkB0 + 8) * BN + c4B * 4;

    float4 av  = *(const float4*)(Aptr);
    float4 bv0 = *(const float4*)(Bptr0);
    float4 bv1 = *(const float4*)(Bptr1);

    As[0][c4A * 4 + 0][rowA] = av.x;
    As[0][c4A * 4 + 1][rowA] = av.y;
    As[0][c4A * 4 + 2][rowA] = av.z;
    As[0][c4A * 4 + 3][rowA] = av.w;
    *(float4*)&Bs[0][kkB0][c4B * 4]     = bv0;
    *(float4*)&Bs[0][kkB0 + 8][c4B * 4] = bv1;
    __syncthreads();

    int cur = 0;
    for (int tt = 0; tt < nT; tt++) {
        if (tt + 1 < nT) {
            int k0n = (tt + 1) * BK;
            av  = *(const float4*)(Aptr + k0n);
            bv0 = *(const float4*)(Bptr0 + (size_t)k0n * BN);
            bv1 = *(const float4*)(Bptr1 + (size_t)k0n * BN);
        }

#pragma unroll
        for (int kk = 0; kk < BK; kk++) {
            ulonglong2 a01 = *(const ulonglong2*)&As[cur][kk][ty * 8];
            ulonglong2 a23 = *(const ulonglong2*)&As[cur][kk][ty * 8 + 4];
            float4 b = *(const float4*)&Bs[cur][kk][tx * 4];
            unsigned long long B0, B1, B2, B3;
            asm("mov.b64 %0, {%1, %1};" : "=l"(B0) : "f"(b.x));
            asm("mov.b64 %0, {%1, %1};" : "=l"(B1) : "f"(b.y));
            asm("mov.b64 %0, {%1, %1};" : "=l"(B2) : "f"(b.z));
            asm("mov.b64 %0, {%1, %1};" : "=l"(B3) : "f"(b.w));
            unsigned long long ap[4] = {a01.x, a01.y, a23.x, a23.y};
#pragma unroll
            for (int p = 0; p < 4; p++) {
                asm("fma.rn.f32x2 %0, %1, %2, %0;" : "+l"(acc[p][0]) : "l"(ap[p]), "l"(B0));
                asm("fma.rn.f32x2 %0, %1, %2, %0;" : "+l"(acc[p][1]) : "l"(ap[p]), "l"(B1));
                asm("fma.rn.f32x2 %0, %1, %2, %0;" : "+l"(acc[p][2]) : "l"(ap[p]), "l"(B2));
                asm("fma.rn.f32x2 %0, %1, %2, %0;" : "+l"(acc[p][3]) : "l"(ap[p]), "l"(B3));
            }
        }

        if (tt + 1 < nT) {
            int nxt = cur ^ 1;
            As[nxt][c4A * 4 + 0][rowA] = av.x;
            As[nxt][c4A * 4 + 1][rowA] = av.y;
            As[nxt][c4A * 4 + 2][rowA] = av.z;
            As[nxt][c4A * 4 + 3][rowA] = av.w;
            *(float4*)&Bs[nxt][kkB0][c4B * 4]     = bv0;
            *(float4*)&Bs[nxt][kkB0 + 8][c4B * 4] = bv1;
        }
        __syncthreads();
        cur ^= 1;
    }

    float4 bvb = *(const float4*)(bias + tx * 4);
#pragma unroll
    for (int p = 0; p < 4; p++) {
        float lo[4], hi[4];
#pragma unroll
        for (int j = 0; j < 4; j++) {
            float l, h;
            asm("mov.b64 {%0, %1}, %2;" : "=f"(l), "=f"(h) : "l"(acc[p][j]));
            lo[j] = l; hi[j] = h;
        }
        int r0 = bm + ty * 8 + 2 * p;
        float4 o0, o1;
        o0.x = fmaxf(lo[0] + bvb.x, 0.f); o0.y = fmaxf(lo[1] + bvb.y, 0.f);
        o0.z = fmaxf(lo[2] + bvb.z, 0.f); o0.w = fmaxf(lo[3] + bvb.w, 0.f);
        o1.x = fmaxf(hi[0] + bvb.x, 0.f); o1.y = fmaxf(hi[1] + bvb.y, 0.f);
        o1.z = fmaxf(hi[2] + bvb.z, 0.f); o1.w = fmaxf(hi[3] + bvb.w, 0.f);
        *(float4*)(H + (size_t)r0 * DV + tx * 4)       = o0;
        *(float4*)(H + (size_t)(r0 + 1) * DV + tx * 4) = o1;
    }
}

// ---------------------------------------------------------------------------
// Degree histogram, privatized: NPART blocks, each builds a 4096-entry smem
// histogram over its slice of the 2E index stream (eab cols ++ eba rows),
// then stores its partial with vectorized coalesced stores.
// ---------------------------------------------------------------------------
__global__ void __launch_bounds__(256) deg_part_kernel(
    const int* __restrict__ eab, const int* __restrict__ eba, int E)
{
    __shared__ int h[NMAX];
    const int t = threadIdx.x;
    for (int i = t; i < NMAX / 4; i += blockDim.x) ((int4*)h)[i] = make_int4(0, 0, 0, 0);
    __syncthreads();

    const int s = g_mode64 ? 2 : 1;
    const int total = 2 * E;
    const int per = (total + NPART - 1) / NPART;
    const int lo = blockIdx.x * per;
    const int hi = min(lo + per, total);

    for (int j = lo + t; j < hi; j += blockDim.x) {
        int idx;
        if (j < E) idx = eab[(size_t)(E + j) * s];        // edge_ab[1][j]
        else       idx = eba[(size_t)(j - E) * s];        // edge_ba[0][j-E]
        atomicAdd(&h[idx], 1);
    }
    __syncthreads();

    for (int i = t; i < NMAX / 4; i += blockDim.x)
        ((int4*)g_part[blockIdx.x])[i] = ((int4*)h)[i];
}

// ---------------------------------------------------------------------------
// t[row] += h_a[col] for each edge in edge_ba. One warp per edge,
// one red.global.add.v4.f32 (16B) per lane.
// ---------------------------------------------------------------------------
__global__ void scatter1_kernel(const int* __restrict__ e, int E) {
    int gw   = (blockIdx.x * blockDim.x + threadIdx.x) >> 5;
    int lane = threadIdx.x & 31;
    if (gw >= E) return;
    int s   = g_mode64 ? 2 : 1;
    int row = e[(size_t)gw * s];
    int col = e[(size_t)(E + gw) * s];
    float4 v = *(const float4*)(g_ha + (size_t)col * DV + lane * 4);
    float* p = g_t + (size_t)row * DV + lane * 4;
    asm volatile("red.global.add.v4.f32 [%0], {%1,%2,%3,%4};"
                 :: "l"(p), "f"(v.x), "f"(v.y), "f"(v.z), "f"(v.w) : "memory");
}

// ---------------------------------------------------------------------------
// Fused degree-reduce + combine. One warp per row:
//   deg = sum_p g_part[p][row]        (redux.sync across the warp)
//   t[row,:] = d(deg) * t[row,:] + h_b[row,:]
// ---------------------------------------------------------------------------
__global__ void __launch_bounds__(256) combine_kernel(int nrows) {
    int gw   = (blockIdx.x * blockDim.x + threadIdx.x) >> 5;   // row
    int lane = threadIdx.x & 31;
    if (gw >= nrows) return;

    int s = g_part[lane][gw] + g_part[lane + 32][gw];
    s = __reduce_add_sync(0xffffffffu, s);
    float d = s > 0 ? 1.0f / (float)s : 0.0f;

    size_t i = (size_t)gw * (DV / 4) + lane;
    float4 tv = ((float4*)g_t)[i];
    float4 hb = ((float4*)g_hb)[i];
    float4 o;
    o.x = d * tv.x + hb.x;
    o.y = d * tv.y + hb.y;
    o.z = d * tv.z + hb.z;
    o.w = d * tv.w + hb.w;
    ((float4*)g_t)[i] = o;
}

// ---------------------------------------------------------------------------
// out[row] += t[col] for each edge in edge_ab.
// ---------------------------------------------------------------------------
__global__ void scatter2_kernel(const int* __restrict__ e, int E,
                                float* __restrict__ out) {
    int gw   = (blockIdx.x * blockDim.x + threadIdx.x) >> 5;
    int lane = threadIdx.x & 31;
    if (gw >= E) return;
    int s   = g_mode64 ? 2 : 1;
    int row = e[(size_t)gw * s];
    int col = e[(size_t)(E + gw) * s];
    float4 v = *(const float4*)(g_t + (size_t)col * DV + lane * 4);
    float* p = out + (size_t)row * DV + lane * 4;
    asm volatile("red.global.add.v4.f32 [%0], {%1,%2,%3,%4};"
                 :: "l"(p), "f"(v.x), "f"(v.y), "f"(v.z), "f"(v.w) : "memory");
}

// ---------------------------------------------------------------------------
extern "C" void kernel_launch(void* const* d_in, const int* in_sizes, int n_in,
                              void* d_out, int out_size) {
    const float* x_a = (const float*)d_in[0];
    const float* x_b = (const float*)d_in[1];
    const float* W_a = (const float*)d_in[2];
    const float* b_a = (const float*)d_in[3];
    const float* W_b = (const float*)d_in[4];
    const float* b_b = (const float*)d_in[5];
    const int*   eab = (const int*)d_in[6];
    const int*   eba = (const int*)d_in[7];
    float* out = (float*)d_out;

    const int D  = in_sizes[3];          // 128
    const int Fa = in_sizes[2] / D;      // 512
    const int Na = in_sizes[0] / Fa;     // 4096
    const int E  = in_sizes[6] / 2;      // 131072

    const int nElem = Na * D;

    // 1. zero t/out + dtype detection (fused)
    {
        int n4 = nElem / 4;
        int nw = 2 * E < 2048 ? 2 * E : 2048;
        zero_detect_kernel<<<(n4 + 255) / 256, 256>>>(out, nElem, eab, nw);
    }

    // 2. fused feature projections (both GEMMs in one launch, 1 wave)
    {
        int blocksPer = Na / 64;
        gemm2_relu_kernel<<<2 * blocksPer, 256>>>(x_a, W_a, b_a, x_b, W_b, b_b, Fa, blocksPer);
    }

    // 3. degree histogram partials (reduce is fused into combine)
    deg_part_kernel<<<NPART, 256>>>(eab, eba, E);

    // 4. t = B @ h_a  (scatter over edge_ba)
    {
        long long thr = (long long)E * 32;
        scatter1_kernel<<<(unsigned)((thr + 255) / 256), 256>>>(eba, E);
    }

    // 5. t = d * t + h_b   (one warp per row; degree reduced in-warp)
    {
        long long thr = (long long)Na * 32;
        combine_kernel<<<(unsigned)((thr + 255) / 256), 256>>>(Na);
    }

    // 6. out = A @ t  (scatter over edge_ab)
    {
        long long thr = (long long)E * 32;
        scatter2_kernel<<<(unsigned)((thr + 255) / 256), 256>>>(eab, E, out);
    }
}